// round 4
// baseline (speedup 1.0000x reference)
#include <cuda_runtime.h>

#define BB 64
#define WW 128
#define FF 64
#define OUTF 64
#define CH 128
#define TI 16

typedef unsigned long long ull;

// Scratch: projected features (with bias)
__device__ float g_fsrc[BB * WW * CH];
__device__ float g_fdst[BB * WW * CH];

// ---- packed f32x2 helpers ----
__device__ __forceinline__ ull fma2(ull a, ull b, ull c) {
    ull d; asm("fma.rn.f32x2 %0, %1, %2, %3;" : "=l"(d) : "l"(a), "l"(b), "l"(c)); return d;
}
__device__ __forceinline__ ull add2(ull a, ull b) {
    ull d; asm("add.rn.f32x2 %0, %1, %2;" : "=l"(d) : "l"(a), "l"(b)); return d;
}
__device__ __forceinline__ ull dup2(float a) {
    ull d; asm("mov.b64 %0, {%1, %1};" : "=l"(d) : "f"(a)); return d;
}
__device__ __forceinline__ float lo2(ull v) { return __uint_as_float((unsigned)(v & 0xffffffffu)); }
__device__ __forceinline__ float hi2(ull v) { return __uint_as_float((unsigned)(v >> 32)); }
__device__ __forceinline__ float hsum2(ull v) { return lo2(v) + hi2(v); }
#define ABSMASK 0x7fffffff7fffffffULL

// 16B-chunk swizzle within a 64-float (16-chunk) row
__device__ __forceinline__ int swz16(int row, int c) { return (c & 8) | ((c ^ row) & 7); }

// ---------------------------------------------------------------------------
// Kernel 1: projections + zero-init of out.
// C[8192 x 256] = X[8192 x 64] @ W^T + bias. grid (4, 128), 256 threads.
// ---------------------------------------------------------------------------
__global__ __launch_bounds__(256) void proj_kernel(
    const float* __restrict__ x,
    const float* __restrict__ w_src, const float* __restrict__ b_src,
    const float* __restrict__ w_dst, const float* __restrict__ b_dst,
    float* __restrict__ out)
{
    __shared__ float xs[64 * 68];
    __shared__ float ws[64 * 68];

    const int tid = threadIdx.x;
    const int ot = blockIdx.x;           // 0..3
    const int row0 = blockIdx.y * 64;
    const bool is_src = (ot < 2);
    const float* __restrict__ wm = is_src ? w_src : w_dst;
    const float* __restrict__ bv = is_src ? b_src : b_dst;
    const int obase = (ot & 1) * 64;

    // zero-init out (512 blocks x 256 threads x float4 == 2MB exactly)
    {
        float4 z = make_float4(0.f, 0.f, 0.f, 0.f);
        ((float4*)out)[(blockIdx.x * 128 + blockIdx.y) * 256 + tid] = z;
    }

    const float4* __restrict__ x4 = (const float4*)(x + row0 * FF);
    const float4* __restrict__ w4 = (const float4*)(wm + obase * FF);
    #pragma unroll
    for (int t = 0; t < 4; t++) {
        int m = tid + 256 * t;          // 1024 float4 per tile
        int r = m >> 4, c4 = m & 15;
        *(float4*)(xs + r * 68 + c4 * 4) = x4[m];
        *(float4*)(ws + r * 68 + c4 * 4) = w4[m];
    }
    __syncthreads();

    const int cx = tid & 15;
    const int ry = tid >> 4;

    ull acc[4][4];
    #pragma unroll
    for (int r = 0; r < 4; r++)
        #pragma unroll
        for (int c = 0; c < 4; c++) acc[r][c] = 0ULL;

    const ulonglong2* __restrict__ xs16 = (const ulonglong2*)xs;
    const ulonglong2* __restrict__ ws16 = (const ulonglong2*)ws;

    #pragma unroll 4
    for (int f4 = 0; f4 < 16; f4++) {
        ulonglong2 xr[4], wv[4];
        #pragma unroll
        for (int r = 0; r < 4; r++) xr[r] = xs16[(ry + 16 * r) * 17 + f4];
        #pragma unroll
        for (int c = 0; c < 4; c++) wv[c] = ws16[(cx + 16 * c) * 17 + f4];
        #pragma unroll
        for (int r = 0; r < 4; r++)
            #pragma unroll
            for (int c = 0; c < 4; c++) {
                acc[r][c] = fma2(xr[r].x, wv[c].x, acc[r][c]);
                acc[r][c] = fma2(xr[r].y, wv[c].y, acc[r][c]);
            }
    }

    float* __restrict__ dst = is_src ? g_fsrc : g_fdst;
    #pragma unroll
    for (int c = 0; c < 4; c++) {
        int oloc = obase + cx + 16 * c;
        float bias = bv[oloc];
        #pragma unroll
        for (int r = 0; r < 4; r++) {
            int bw = row0 + ry + 16 * r;
            dst[bw * CH + oloc] = hsum2(acc[r][c]) + bias;
        }
    }
}

// ---------------------------------------------------------------------------
// Kernel 2: attention, HEAD-SPLIT, R=4 score tiling.
// grid (8 i-tiles, 64 b, 2 h), 256 threads.
// warp = (wg = w&3, jh = w>>2): i rows {wg+4r}, j in jh*64 + {jt + 32c}, c<2.
// smem (floats):
//   fsrc_h [128 x 64]  swizzled 16B chunks       0 .. 8192
//   fdst_h [16 x 68]   padded                 8192 .. 9280   (reused as red)
//   alpha2 [16 x 128]  DUPLICATED f32 pairs   9280 .. 13376
//   a04    [64]                              13376 .. 13440
//   sA     [128]                             13440 .. 13568  (1.5-prescaled)
//   dA     [16]                              13568 .. 13584
//   sm_m   [16 x 2]                          13584 .. 13616  (softmax max partials)
//   sm_s   [16 x 2]                          13616 .. 13648  (softmax sum partials)
// ---------------------------------------------------------------------------
#define OFF_FDST  8192
#define OFF_ALPHA 9280
#define OFF_A04   13376
#define OFF_SA    13440
#define OFF_DA    13568
#define OFF_SMM   13584
#define OFF_SMS   13616
#define SM_FLOATS 13648
#define SM_BYTES  (SM_FLOATS * 4)

__global__ __launch_bounds__(256, 4) void attn_kernel(
    const float* __restrict__ attn_w,
    float* __restrict__ out)
{
    extern __shared__ float sm[];
    float* fsrc_sm = sm;
    float* fdst_sm = sm + OFF_FDST;
    ull*   alpha2  = (ull*)(sm + OFF_ALPHA);
    float* a04     = sm + OFF_A04;
    float* sA      = sm + OFF_SA;
    float* dA      = sm + OFF_DA;
    float* sm_m    = sm + OFF_SMM;
    float* sm_s    = sm + OFF_SMS;

    const int tid = threadIdx.x;
    const int b  = blockIdx.y;
    const int i0 = blockIdx.x * TI;
    const int h  = blockIdx.z;

    ulonglong2* fs16 = (ulonglong2*)fsrc_sm;

    // ---- fill fsrc_h: 128 rows x 16 chunks (swizzled, STS.128) ----
    {
        const float4* __restrict__ g4 = (const float4*)(g_fsrc + b * WW * CH + h * 64);
        #pragma unroll
        for (int t = 0; t < 8; t++) {
            int m = tid + 256 * t;           // 2048 chunks
            int j = m >> 4, c = m & 15;
            float4 v = g4[j * 32 + c];
            *(float4*)(fsrc_sm + j * 64 + swz16(j, c) * 4) = v;
        }
    }
    // ---- fill fdst_h tile: 16 rows x 16 chunks, padded stride 68 ----
    {
        const float4* __restrict__ g4 = (const float4*)(g_fdst + (b * WW + i0) * CH + h * 64);
        int i = tid >> 4, c = tid & 15;
        *(float4*)(fdst_sm + i * 68 + c * 4) = g4[i * 32 + c];
    }
    if (tid < 64) a04[tid] = 0.4f * attn_w[h * 64 + tid];
    __syncthreads();

    // ---- per-node dots (1.5-prescaled linear leakyrelu component) ----
    if (tid < 128) {               // sA[j]
        int j = tid;
        const ulonglong2* a16 = (const ulonglong2*)a04;
        ull acc = 0ULL;
        #pragma unroll
        for (int f4 = 0; f4 < 16; f4++) {
            ulonglong2 sv = fs16[j * 16 + swz16(j, f4)];
            ulonglong2 av = a16[f4];
            acc = fma2(av.x, sv.x, acc);
            acc = fma2(av.y, sv.y, acc);
        }
        sA[j] = 1.5f * hsum2(acc);
    } else if (tid < 144) {        // dA[i]
        int il = tid - 128;
        const ulonglong2* d16 = (const ulonglong2*)(fdst_sm + il * 68);
        const ulonglong2* a16 = (const ulonglong2*)a04;
        ull acc = 0ULL;
        #pragma unroll
        for (int f4 = 0; f4 < 16; f4++) {
            ulonglong2 dv = d16[f4];
            ulonglong2 av = a16[f4];
            acc = fma2(av.x, dv.x, acc);
            acc = fma2(av.y, dv.y, acc);
        }
        dA[il] = 1.5f * hsum2(acc);
    }
    __syncthreads();

    // ---- score: warp (wg, jh); i rows {wg+4r}, j = jh*64 + jt + 32c ----
    const int jt = tid & 31;
    const int w  = tid >> 5;
    const int wg = w & 3;
    const int jh = w >> 2;
    const int j0 = jh * 64 + jt;

    ull acc2[4][2];
    #pragma unroll
    for (int r = 0; r < 4; r++) {
        acc2[r][0] = 0ULL; acc2[r][1] = 0ULL;
    }

    {
        const ulonglong2* a16 = (const ulonglong2*)a04;
        #pragma unroll 4
        for (int f4 = 0; f4 < 16; f4++) {
            ulonglong2 av = a16[f4];
            int cs = swz16(j0, f4);                  // j0 and j0+32 share low-3 bits
            ulonglong2 sv0 = fs16[j0 * 16 + cs];
            ulonglong2 sv1 = fs16[(j0 + 32) * 16 + cs];
            ulonglong2 dv[4];
            #pragma unroll
            for (int r = 0; r < 4; r++)
                dv[r] = *(const ulonglong2*)(fdst_sm + (wg + 4 * r) * 68 + f4 * 4);
            #pragma unroll
            for (int r = 0; r < 4; r++) {
                ull t0 = add2(sv0.x, dv[r].x) & ABSMASK;
                acc2[r][0] = fma2(av.x, t0, acc2[r][0]);
                ull t1 = add2(sv0.y, dv[r].y) & ABSMASK;
                acc2[r][0] = fma2(av.y, t1, acc2[r][0]);
                ull u0 = add2(sv1.x, dv[r].x) & ABSMASK;
                acc2[r][1] = fma2(av.x, u0, acc2[r][1]);
                ull u1 = add2(sv1.y, dv[r].y) & ABSMASK;
                acc2[r][1] = fma2(av.y, u1, acc2[r][1]);
            }
        }
    }

    // ---- softmax over j (2-warp split per row via smem partials) ----
    float e[4][2];
    {
        float sA0 = sA[j0], sA1 = sA[j0 + 32];
        #pragma unroll
        for (int r = 0; r < 4; r++) {
            int il = wg + 4 * r;
            float dv = dA[il];
            e[r][0] = sA0 + dv + hsum2(acc2[r][0]);
            e[r][1] = sA1 + dv + hsum2(acc2[r][1]);
            float m = fmaxf(e[r][0], e[r][1]);
            #pragma unroll
            for (int off = 16; off > 0; off >>= 1)
                m = fmaxf(m, __shfl_xor_sync(0xffffffffu, m, off));
            if (jt == 0) sm_m[il * 2 + jh] = m;
        }
    }
    __syncthreads();

    float p[4][2];
    #pragma unroll
    for (int r = 0; r < 4; r++) {
        int il = wg + 4 * r;
        float m = fmaxf(sm_m[il * 2], sm_m[il * 2 + 1]);
        p[r][0] = __expf(e[r][0] - m);
        p[r][1] = __expf(e[r][1] - m);
        float s = p[r][0] + p[r][1];
        #pragma unroll
        for (int off = 16; off > 0; off >>= 1)
            s += __shfl_xor_sync(0xffffffffu, s, off);
        if (jt == 0) sm_s[il * 2 + jh] = s;
    }
    __syncthreads();

    #pragma unroll
    for (int r = 0; r < 4; r++) {
        int il = wg + 4 * r;
        float inv = 1.0f / (sm_s[il * 2] + sm_s[il * 2 + 1]);
        alpha2[il * WW + j0]      = dup2(p[r][0] * inv);
        alpha2[il * WW + j0 + 32] = dup2(p[r][1] * inv);
    }
    __syncthreads();

    // ---- aggregation: jh = j-half, r4 -> i rows {r4+4k}, f2 = float pair ----
    const int jhA = tid >> 7;
    const int r4 = (tid >> 5) & 3;
    const int f2 = tid & 31;

    ull accA[4];
    #pragma unroll
    for (int k = 0; k < 4; k++) accA[k] = 0ULL;

    {
        const ulonglong2* A2 = (const ulonglong2*)alpha2;   // [row][64 j-pairs]
        const ull* fs8 = (const ull*)fsrc_sm;               // 32 per row
        const int c0 = f2 >> 1;
        const int half = f2 & 1;

        #pragma unroll 4
        for (int jp = 0; jp < 32; jp++) {
            int jp2 = jhA * 32 + jp;
            int ja = 2 * jp2, jb = ja + 1;
            ulonglong2 al[4];
            #pragma unroll
            for (int k = 0; k < 4; k++)
                al[k] = A2[(r4 + 4 * k) * 64 + jp2];        // broadcast
            ull s0 = fs8[ja * 32 + swz16(ja, c0) * 2 + half];
            ull s1 = fs8[jb * 32 + swz16(jb, c0) * 2 + half];
            #pragma unroll
            for (int k = 0; k < 4; k++) {
                accA[k] = fma2(al[k].x, s0, accA[k]);
                accA[k] = fma2(al[k].y, s1, accA[k]);
            }
        }
    }

    // ---- cross-half reduction + atomic add into out ----
    __syncthreads();
    {
        ull* red = (ull*)fdst_sm;            // 128 x 4 ull = 4KB scratch
        if (jhA == 1) {
            int base = (tid & 127) * 4;
            #pragma unroll
            for (int k = 0; k < 4; k++) red[base + k] = accA[k];
        }
        __syncthreads();
        if (jhA == 0) {
            const ull* rr = red + tid * 4;
            #pragma unroll
            for (int k = 0; k < 4; k++) {
                ull s = add2(accA[k], rr[k]);
                int i = i0 + r4 + 4 * k;
                float* op = out + (b * WW + i) * OUTF + f2 * 2;
                atomicAdd(op,     0.5f * lo2(s));
                atomicAdd(op + 1, 0.5f * hi2(s));
            }
        }
    }
}

// ---------------------------------------------------------------------------
extern "C" void kernel_launch(void* const* d_in, const int* in_sizes, int n_in,
                              void* d_out, int out_size)
{
    (void)in_sizes; (void)n_in; (void)out_size;
    const float* x      = (const float*)d_in[0];
    const float* w_src  = (const float*)d_in[1];
    const float* b_src  = (const float*)d_in[2];
    const float* w_dst  = (const float*)d_in[3];
    const float* b_dst  = (const float*)d_in[4];
    const float* attn_w = (const float*)d_in[5];
    float* out = (float*)d_out;

    cudaFuncSetAttribute(attn_kernel,
                         cudaFuncAttributeMaxDynamicSharedMemorySize,
                         SM_BYTES);

    proj_kernel<<<dim3(4, 128), 256>>>(x, w_src, b_src, w_dst, b_dst, out);
    attn_kernel<<<dim3(WW / TI, BB, 2), 256, SM_BYTES>>>(attn_w, out);
}

// round 5
// speedup vs baseline: 1.0455x; 1.0455x over previous
#include <cuda_runtime.h>

#define BB 64
#define WW 128
#define FF 64
#define OUTF 64
#define CH 128
#define TI 16
#define PARTN (BB * WW * OUTF)

typedef unsigned long long ull;

// Scratch: projected features (with bias), per-head partial outputs
__device__ float g_fsrc[BB * WW * CH];
__device__ float g_fdst[BB * WW * CH];
__device__ float g_part[2 * PARTN];

// ---- packed f32x2 helpers ----
__device__ __forceinline__ ull fma2(ull a, ull b, ull c) {
    ull d; asm("fma.rn.f32x2 %0, %1, %2, %3;" : "=l"(d) : "l"(a), "l"(b), "l"(c)); return d;
}
__device__ __forceinline__ ull add2(ull a, ull b) {
    ull d; asm("add.rn.f32x2 %0, %1, %2;" : "=l"(d) : "l"(a), "l"(b)); return d;
}
__device__ __forceinline__ ull dup2(float a) {
    ull d; asm("mov.b64 %0, {%1, %1};" : "=l"(d) : "f"(a)); return d;
}
__device__ __forceinline__ float lo2(ull v) { return __uint_as_float((unsigned)(v & 0xffffffffu)); }
__device__ __forceinline__ float hi2(ull v) { return __uint_as_float((unsigned)(v >> 32)); }
__device__ __forceinline__ float hsum2(ull v) { return lo2(v) + hi2(v); }
#define ABSMASK 0x7fffffff7fffffffULL

// 16B-chunk swizzle within a 64-float (16-chunk) row
__device__ __forceinline__ int swz16(int row, int c) { return (c & 8) | ((c ^ row) & 7); }

// ---------------------------------------------------------------------------
// Kernel 1: projections. C[8192 x 256] = X[8192 x 64] @ W^T + bias.
// grid (4, 128), 256 threads, float4 smem, f32x2 packed accumulation.
// ---------------------------------------------------------------------------
__global__ __launch_bounds__(256) void proj_kernel(
    const float* __restrict__ x,
    const float* __restrict__ w_src, const float* __restrict__ b_src,
    const float* __restrict__ w_dst, const float* __restrict__ b_dst)
{
    __shared__ float xs[64 * 68];
    __shared__ float ws[64 * 68];

    const int tid = threadIdx.x;
    const int ot = blockIdx.x;           // 0..3
    const int row0 = blockIdx.y * 64;
    const bool is_src = (ot < 2);
    const float* __restrict__ wm = is_src ? w_src : w_dst;
    const float* __restrict__ bv = is_src ? b_src : b_dst;
    const int obase = (ot & 1) * 64;

    const float4* __restrict__ x4 = (const float4*)(x + row0 * FF);
    const float4* __restrict__ w4 = (const float4*)(wm + obase * FF);
    #pragma unroll
    for (int t = 0; t < 4; t++) {
        int m = tid + 256 * t;          // 1024 float4 per tile
        int r = m >> 4, c4 = m & 15;
        *(float4*)(xs + r * 68 + c4 * 4) = x4[m];
        *(float4*)(ws + r * 68 + c4 * 4) = w4[m];
    }
    __syncthreads();

    const int cx = tid & 15;
    const int ry = tid >> 4;

    ull acc[4][4];
    #pragma unroll
    for (int r = 0; r < 4; r++)
        #pragma unroll
        for (int c = 0; c < 4; c++) acc[r][c] = 0ULL;

    const ulonglong2* __restrict__ xs16 = (const ulonglong2*)xs;
    const ulonglong2* __restrict__ ws16 = (const ulonglong2*)ws;

    #pragma unroll 4
    for (int f4 = 0; f4 < 16; f4++) {
        ulonglong2 xr[4], wv[4];
        #pragma unroll
        for (int r = 0; r < 4; r++) xr[r] = xs16[(ry + 16 * r) * 17 + f4];
        #pragma unroll
        for (int c = 0; c < 4; c++) wv[c] = ws16[(cx + 16 * c) * 17 + f4];
        #pragma unroll
        for (int r = 0; r < 4; r++)
            #pragma unroll
            for (int c = 0; c < 4; c++) {
                acc[r][c] = fma2(xr[r].x, wv[c].x, acc[r][c]);
                acc[r][c] = fma2(xr[r].y, wv[c].y, acc[r][c]);
            }
    }

    float* __restrict__ dst = is_src ? g_fsrc : g_fdst;
    #pragma unroll
    for (int c = 0; c < 4; c++) {
        int oloc = obase + cx + 16 * c;
        float bias = bv[oloc];
        #pragma unroll
        for (int r = 0; r < 4; r++) {
            int bw = row0 + ry + 16 * r;
            dst[bw * CH + oloc] = hsum2(acc[r][c]) + bias;
        }
    }
}

// ---------------------------------------------------------------------------
// Kernel 2: attention, HEAD-SPLIT. grid (8 i-tiles, 64 b, 2 h), 256 threads.
// Score/softmax = round-3 shape (warp owns 2 rows, in-warp softmax).
// Aggregation = j-quarter split, 4-f-wide threads, plain STG epilogue.
// smem (floats):
//   fsrc_h [128 x 64]  swizzled 16B chunks       0 .. 8192
//   fdst_h [16 x 68]   padded                 8192 .. 9280
//   alpha2 [16 x 128]  DUP f32 pairs          9280 .. 13376  (reused as red)
//   a04    [64]                              13376 .. 13440
//   sA     [128]                             13440 .. 13568  (1.5-prescaled)
//   dA     [16]                              13568 .. 13584
// ---------------------------------------------------------------------------
#define OFF_FDST  8192
#define OFF_ALPHA 9280
#define OFF_A04   13376
#define OFF_SA    13440
#define OFF_DA    13568
#define SM_FLOATS 13584
#define SM_BYTES  (SM_FLOATS * 4)

__global__ __launch_bounds__(256, 4) void attn_kernel(const float* __restrict__ attn_w)
{
    extern __shared__ float sm[];
    float* fsrc_sm = sm;
    float* fdst_sm = sm + OFF_FDST;
    ull*   alpha2  = (ull*)(sm + OFF_ALPHA);
    float* a04     = sm + OFF_A04;
    float* sA      = sm + OFF_SA;
    float* dA      = sm + OFF_DA;

    const int tid = threadIdx.x;
    const int b  = blockIdx.y;
    const int i0 = blockIdx.x * TI;
    const int h  = blockIdx.z;

    ulonglong2* fs16 = (ulonglong2*)fsrc_sm;

    // ---- fill fsrc_h: 128 rows x 16 chunks (swizzled, STS.128) ----
    {
        const float4* __restrict__ g4 = (const float4*)(g_fsrc + b * WW * CH + h * 64);
        #pragma unroll
        for (int t = 0; t < 8; t++) {
            int m = tid + 256 * t;           // 2048 chunks
            int j = m >> 4, c = m & 15;
            float4 v = g4[j * 32 + c];
            *(float4*)(fsrc_sm + j * 64 + swz16(j, c) * 4) = v;
        }
    }
    // ---- fill fdst_h tile: 16 rows x 16 chunks, padded stride 68 ----
    {
        const float4* __restrict__ g4 = (const float4*)(g_fdst + (b * WW + i0) * CH + h * 64);
        int i = tid >> 4, c = tid & 15;
        *(float4*)(fdst_sm + i * 68 + c * 4) = g4[i * 32 + c];
    }
    if (tid < 64) a04[tid] = 0.4f * attn_w[h * 64 + tid];
    __syncthreads();

    // ---- per-node dots (1.5-prescaled linear leakyrelu component) ----
    if (tid < 128) {               // sA[j]
        int j = tid;
        const ulonglong2* a16 = (const ulonglong2*)a04;
        ull acc = 0ULL;
        #pragma unroll
        for (int f4 = 0; f4 < 16; f4++) {
            ulonglong2 sv = fs16[j * 16 + swz16(j, f4)];
            ulonglong2 av = a16[f4];
            acc = fma2(av.x, sv.x, acc);
            acc = fma2(av.y, sv.y, acc);
        }
        sA[j] = 1.5f * hsum2(acc);
    } else if (tid < 144) {        // dA[i]
        int il = tid - 128;
        const ulonglong2* d16 = (const ulonglong2*)(fdst_sm + il * 68);
        const ulonglong2* a16 = (const ulonglong2*)a04;
        ull acc = 0ULL;
        #pragma unroll
        for (int f4 = 0; f4 < 16; f4++) {
            ulonglong2 dv = d16[f4];
            ulonglong2 av = a16[f4];
            acc = fma2(av.x, dv.x, acc);
            acc = fma2(av.y, dv.y, acc);
        }
        dA[il] = 1.5f * hsum2(acc);
    }
    __syncthreads();

    // ---- score: warp w owns i rows {w, w+8}; lanes jt; j = jt + 32c ----
    const int jt = tid & 31;
    const int w  = tid >> 5;

    ull acc2[2][4];
    #pragma unroll
    for (int r = 0; r < 2; r++)
        #pragma unroll
        for (int c = 0; c < 4; c++) acc2[r][c] = 0ULL;

    {
        const ulonglong2* a16 = (const ulonglong2*)a04;
        #pragma unroll 4
        for (int f4 = 0; f4 < 16; f4++) {
            ulonglong2 av = a16[f4];
            ulonglong2 dv[2], sv[4];
            dv[0] = *(const ulonglong2*)(fdst_sm + w * 68 + f4 * 4);
            dv[1] = *(const ulonglong2*)(fdst_sm + (w + 8) * 68 + f4 * 4);
            int cs = swz16(jt, f4);
            #pragma unroll
            for (int c = 0; c < 4; c++)
                sv[c] = fs16[(jt + 32 * c) * 16 + cs];
            #pragma unroll
            for (int r = 0; r < 2; r++)
                #pragma unroll
                for (int c = 0; c < 4; c++) {
                    ull t0 = add2(sv[c].x, dv[r].x) & ABSMASK;
                    acc2[r][c] = fma2(av.x, t0, acc2[r][c]);
                    ull t1 = add2(sv[c].y, dv[r].y) & ABSMASK;
                    acc2[r][c] = fma2(av.y, t1, acc2[r][c]);
                }
        }
    }

    // ---- softmax over j (in-warp), write DUPLICATED alpha pairs ----
    {
        float sAv[4];
        #pragma unroll
        for (int c = 0; c < 4; c++) sAv[c] = sA[jt + 32 * c];

        #pragma unroll
        for (int r = 0; r < 2; r++) {
            int il = w + 8 * r;
            float dv = dA[il];
            float e[4];
            #pragma unroll
            for (int c = 0; c < 4; c++)
                e[c] = sAv[c] + dv + hsum2(acc2[r][c]);

            float m = fmaxf(fmaxf(e[0], e[1]), fmaxf(e[2], e[3]));
            #pragma unroll
            for (int off = 16; off > 0; off >>= 1)
                m = fmaxf(m, __shfl_xor_sync(0xffffffffu, m, off));

            float p[4], ssum = 0.0f;
            #pragma unroll
            for (int c = 0; c < 4; c++) { p[c] = __expf(e[c] - m); ssum += p[c]; }
            #pragma unroll
            for (int off = 16; off > 0; off >>= 1)
                ssum += __shfl_xor_sync(0xffffffffu, ssum, off);

            float inv = 1.0f / ssum;
            #pragma unroll
            for (int c = 0; c < 4; c++)
                alpha2[il * WW + jt + 32 * c] = dup2(p[c] * inv);
        }
    }
    __syncthreads();

    // ---- aggregation: js = j-quarter, ig -> i rows {ig+4k}, fg = 4-float group
    const int fg = tid & 15;
    const int ig = (tid >> 4) & 3;
    const int js = tid >> 6;

    ull accA[4][2];
    #pragma unroll
    for (int k = 0; k < 4; k++) { accA[k][0] = 0ULL; accA[k][1] = 0ULL; }

    {
        const ulonglong2* A2 = (const ulonglong2*)alpha2;   // [row][64 j-pairs]
        #pragma unroll 4
        for (int jp = 0; jp < 16; jp++) {
            int jp2 = js * 16 + jp;
            int ja = 2 * jp2, jb = ja + 1;
            ulonglong2 al[4];
            #pragma unroll
            for (int k = 0; k < 4; k++)
                al[k] = A2[(ig + 4 * k) * 64 + jp2];        // 2 addrs/warp
            ulonglong2 s0 = fs16[ja * 16 + swz16(ja, fg)];  // 4 floats of row ja
            ulonglong2 s1 = fs16[jb * 16 + swz16(jb, fg)];
            #pragma unroll
            for (int k = 0; k < 4; k++) {
                accA[k][0] = fma2(al[k].x, s0.x, accA[k][0]);
                accA[k][1] = fma2(al[k].x, s0.y, accA[k][1]);
                accA[k][0] = fma2(al[k].y, s1.x, accA[k][0]);
                accA[k][1] = fma2(al[k].y, s1.y, accA[k][1]);
            }
        }
    }

    // ---- cross-quarter reduction (scratch reuses alpha region) + STG ----
    __syncthreads();                    // all alpha/fsrc reads done
    {
        ull* red = (ull*)alpha2;        // 2048 ull available; need 192*9=1728
        const int t64 = tid & 63;
        if (js > 0) {
            int base = ((js - 1) * 64 + t64) * 9;   // stride 9 -> 2-way max conflict
            #pragma unroll
            for (int k = 0; k < 4; k++) {
                red[base + 2 * k]     = accA[k][0];
                red[base + 2 * k + 1] = accA[k][1];
            }
        }
        __syncthreads();
        if (js == 0) {
            float* part = g_part + h * PARTN;
            #pragma unroll
            for (int q = 1; q < 4; q++) {
                const ull* rr = red + ((q - 1) * 64 + t64) * 9;
                #pragma unroll
                for (int k = 0; k < 4; k++) {
                    accA[k][0] = add2(accA[k][0], rr[2 * k]);
                    accA[k][1] = add2(accA[k][1], rr[2 * k + 1]);
                }
            }
            #pragma unroll
            for (int k = 0; k < 4; k++) {
                int i = i0 + ig + 4 * k;
                float4 o;
                o.x = lo2(accA[k][0]); o.y = hi2(accA[k][0]);
                o.z = lo2(accA[k][1]); o.w = hi2(accA[k][1]);
                *(float4*)(part + (b * WW + i) * OUTF + fg * 4) = o;
            }
        }
    }
}

// ---------------------------------------------------------------------------
// Kernel 3: combine heads. out = 0.5 * (part0 + part1). 512 x 256 float4.
// ---------------------------------------------------------------------------
__global__ __launch_bounds__(256) void combine_kernel(float* __restrict__ out)
{
    int m = blockIdx.x * 256 + threadIdx.x;
    const float4* p0 = (const float4*)g_part;
    const float4* p1 = (const float4*)(g_part + PARTN);
    float4 a = p0[m], c = p1[m];
    float4 o;
    o.x = 0.5f * (a.x + c.x);
    o.y = 0.5f * (a.y + c.y);
    o.z = 0.5f * (a.z + c.z);
    o.w = 0.5f * (a.w + c.w);
    ((float4*)out)[m] = o;
}

// ---------------------------------------------------------------------------
extern "C" void kernel_launch(void* const* d_in, const int* in_sizes, int n_in,
                              void* d_out, int out_size)
{
    (void)in_sizes; (void)n_in; (void)out_size;
    const float* x      = (const float*)d_in[0];
    const float* w_src  = (const float*)d_in[1];
    const float* b_src  = (const float*)d_in[2];
    const float* w_dst  = (const float*)d_in[3];
    const float* b_dst  = (const float*)d_in[4];
    const float* attn_w = (const float*)d_in[5];
    float* out = (float*)d_out;

    cudaFuncSetAttribute(attn_kernel,
                         cudaFuncAttributeMaxDynamicSharedMemorySize,
                         SM_BYTES);

    proj_kernel<<<dim3(4, 128), 256>>>(x, w_src, b_src, w_dst, b_dst);
    attn_kernel<<<dim3(WW / TI, BB, 2), 256, SM_BYTES>>>(attn_w);
    combine_kernel<<<512, 256>>>(out);
}